// round 16
// baseline (speedup 1.0000x reference)
#include <cuda_runtime.h>
#include <cuda_bf16.h>
#include <math.h>

// Problem constants
#define Bq 128
#define Tq 160
#define Fq 512
#define Eq 64
#define Hq 1024
#define IN0q 576

// ==================== persistent device scratch (no allocs) ====================
__device__ __align__(256) __nv_bfloat16 g_WihH0[4 * Hq * IN0q];
__device__ __align__(256) __nv_bfloat16 g_WihL0[4 * Hq * IN0q];
__device__ __align__(256) __nv_bfloat16 g_WhhH0[4 * Hq * Hq];
__device__ __align__(256) __nv_bfloat16 g_WhhL0[4 * Hq * Hq];
__device__ __align__(256) __nv_bfloat16 g_WihH1[4 * Hq * Hq];
__device__ __align__(256) __nv_bfloat16 g_WihL1[4 * Hq * Hq];
__device__ __align__(256) __nv_bfloat16 g_WhhH1[4 * Hq * Hq];
__device__ __align__(256) __nv_bfloat16 g_WhhL1[4 * Hq * Hq];
__device__ __align__(256) __nv_bfloat16 g_featH[Bq * Tq * Fq];
__device__ __align__(256) __nv_bfloat16 g_featL[Bq * Tq * Fq];
__device__ __align__(256) __nv_bfloat16 g_h0h[Tq * Bq * Hq];
__device__ __align__(256) __nv_bfloat16 g_h0l[Tq * Bq * Hq];
__device__ __align__(256) __nv_bfloat16 g_h1h[Tq * Bq * Hq];
__device__ __align__(256) __nv_bfloat16 g_h1l[Tq * Bq * Hq];
__device__ float g_mu[2][Bq];
__device__ unsigned char g_mask[Bq * Tq];
__device__ unsigned g_bar_ctr;

__device__ __forceinline__ float sigmoidf_(float x) { return 1.0f / (1.0f + expf(-x)); }

__device__ __forceinline__ void split_bf16(float x, __nv_bfloat16& hi, __nv_bfloat16& lo) {
    hi = __float2bfloat16(x);
    lo = __float2bfloat16(x - __bfloat162float(hi));
}

__device__ __forceinline__ unsigned s2u(const void* p) {
    return (unsigned)__cvta_generic_to_shared(p);
}

// ==================== prep kernels ====================
__global__ void mask_norm_kernel(const unsigned char* __restrict__ m_raw)
{
    __shared__ int s_is_u8;
    int tid = threadIdx.x;
    if (tid == 0) { s_is_u8 = 0; g_bar_ctr = 0u; }
    __syncthreads();
    for (int i = tid; i < 1024; i += blockDim.x)
        if (m_raw[4 * i + 1] != 0) atomicOr(&s_is_u8, 1);
    __syncthreads();
    const int is_u8 = s_is_u8;
    const unsigned int* m32 = reinterpret_cast<const unsigned int*>(m_raw);
    for (int i = tid; i < Bq * Tq; i += blockDim.x)
        g_mask[i] = is_u8 ? (m_raw[i] != 0) : (m32[i] != 0u);
    if (tid < 2 * Bq) ((float*)g_mu)[tid] = 0.0f;
}

__global__ void prep_split_kernel(const float* __restrict__ src, int n, int which)
{
    __nv_bfloat16 *hi, *lo;
    switch (which) {
        case 0: hi = g_WihH0; lo = g_WihL0; break;
        case 1: hi = g_WhhH0; lo = g_WhhL0; break;
        case 2: hi = g_WihH1; lo = g_WihL1; break;
        case 3: hi = g_WhhH1; lo = g_WhhL1; break;
        default: hi = g_featH; lo = g_featL; break;
    }
    for (long long i = (long long)blockIdx.x * blockDim.x + threadIdx.x; i < n;
         i += (long long)gridDim.x * blockDim.x) {
        float x = src[i];
        __nv_bfloat16 h = __float2bfloat16(x);
        hi[i] = h;
        lo[i] = __float2bfloat16(x - __bfloat162float(h));
    }
}

// ==================== shared-memory layout ====================
// k16 tile rows padded to 24 bf16 (48B): ldmatrix 8-row reads cover all banks once.
struct K16 {
    __align__(16) __nv_bfloat16 Ah[64 * 24];
    __align__(16) __nv_bfloat16 Al[64 * 24];
    __align__(16) __nv_bfloat16 Bh[64 * 24];
    __align__(16) __nv_bfloat16 Bl[64 * 24];
};
struct CellSmem {
    K16 stg[8];                 // 8 k16 slots = 4 super-slots of K=32 (96 KB)
    float gate[64 * 66];
    float bsum[2][64];          // per-cell bias sums, index g*16+jj
    float mu_s[64];
    unsigned char um_s[64];
};
#define CELL_SMEM_BYTES ((int)sizeof(CellSmem))

// ==================== low-level helpers ====================
__device__ __forceinline__ void cp16(void* dst, const void* src) {
    unsigned d = s2u(dst);
    asm volatile("cp.async.cg.shared.global [%0], [%1], 16;\n" :: "r"(d), "l"(src));
}
__device__ __forceinline__ void cp_commit() { asm volatile("cp.async.commit_group;\n"); }
__device__ __forceinline__ void cp_wait2()  { asm volatile("cp.async.wait_group 2;\n" ::: "memory"); }

__device__ __forceinline__ void mma_bf16(float d[4], const unsigned a[4], const unsigned b[2]) {
    asm volatile(
        "mma.sync.aligned.m16n8k16.row.col.f32.bf16.bf16.f32 "
        "{%0,%1,%2,%3}, {%4,%5,%6,%7}, {%8,%9}, {%0,%1,%2,%3};\n"
        : "+f"(d[0]), "+f"(d[1]), "+f"(d[2]), "+f"(d[3])
        : "r"(a[0]), "r"(a[1]), "r"(a[2]), "r"(a[3]), "r"(b[0]), "r"(b[1]));
}
__device__ __forceinline__ void ldsm_x4(unsigned r[4], unsigned addr) {
    asm volatile("ldmatrix.sync.aligned.m8n8.x4.shared.b16 {%0,%1,%2,%3}, [%4];"
                 : "=r"(r[0]), "=r"(r[1]), "=r"(r[2]), "=r"(r[3]) : "r"(addr));
}
__device__ __forceinline__ void ldsm_x2(unsigned r[2], unsigned addr) {
    asm volatile("ldmatrix.sync.aligned.m8n8.x2.shared.b16 {%0,%1}, [%2];"
                 : "=r"(r[0]), "=r"(r[1]) : "r"(addr));
}

// Software grid barrier: all 128 CTAs co-resident (grid <= SM count, 1 CTA/SM).
__device__ __forceinline__ void grid_barrier(unsigned target)
{
    __syncthreads();
    if (threadIdx.x == 0) {
        asm volatile("red.release.gpu.add.u32 [%0], %1;"
                     :: "l"(&g_bar_ctr), "r"(1u) : "memory");
        unsigned v;
        do {
            asm volatile("ld.acquire.gpu.b32 %0, [%1];"
                         : "=r"(v) : "l"(&g_bar_ctr) : "memory");
        } while (v < target);
    }
    __syncthreads();
}

// ==================== stage fills ====================
// One k16 sub-tile. 256 threads: sel=0 (tid<128) moves A hi/lo, sel=1 moves B hi/lo.
__device__ __forceinline__ void fill_sub(K16* st,
    const __nv_bfloat16* xh, const __nv_bfloat16* xl, long long xstr,
    const __nv_bfloat16* wh, const __nv_bfloat16* wl, int ldW, int k,
    int j0, int row, int half, int sel)
{
    int o = row * 24 + half * 8;
    if (sel == 0) {
        long long xo = (long long)row * xstr + k + half * 8;
        cp16(st->Ah + o, xh + xo);
        cp16(st->Al + o, xl + xo);
    } else {
        int wrow = ((row >> 4) << 10) + j0 + (row & 15);   // gate*Hq + j0 + jj
        long long wo = (long long)wrow * ldW + k + half * 8;
        cp16(st->Bh + o, wh + wo);
        cp16(st->Bl + o, wl + wo);
    }
}

// One K=32 super-chunk = 2 k16 sub-fills into super-slot `slot` (k16 slots 2s, 2s+1).
__device__ __forceinline__ void fill_super(CellSmem* sm, int slot,
    const __nv_bfloat16* xh, const __nv_bfloat16* xl, long long xstr,
    const __nv_bfloat16* wh, const __nv_bfloat16* wl, int ldW, int kbase,
    int j0, int row, int half, int sel)
{
#pragma unroll
    for (int s = 0; s < 2; s++)
        fill_sub(&sm->stg[slot * 2 + s], xh, xl, xstr, wh, wl, ldW, kbase + s * 16,
                 j0, row, half, sel);
}

// One k16 chunk, per-warp 32x16 subtile: 8 LDSM + 12 MMA (3-term bf16 split).
__device__ __forceinline__ void compute_chunk(const K16* st, float acc[2][2][4],
                                              int warp_m, int warp_n, int lane)
{
    unsigned r8 = lane & 7;
    unsigned aoff = ((lane >> 3) & 1) * (8 * 48) + r8 * 48 + ((lane >> 4) & 1) * 16;
    unsigned boff = r8 * 48 + ((lane >> 3) & 1) * 16;
    unsigned ah = s2u(st->Ah), al = s2u(st->Al), bh = s2u(st->Bh), bl = s2u(st->Bl);
    unsigned aH[2][4], aL[2][4], bH[2][2], bL[2][2];
#pragma unroll
    for (int mt = 0; mt < 2; mt++) {
        unsigned base = (unsigned)(warp_m + mt * 16) * 48 + aoff;
        ldsm_x4(aH[mt], ah + base);
        ldsm_x4(aL[mt], al + base);
    }
#pragma unroll
    for (int nt = 0; nt < 2; nt++) {
        unsigned base = (unsigned)(warp_n + nt * 8) * 48 + boff;
        ldsm_x2(bH[nt], bh + base);
        ldsm_x2(bL[nt], bl + base);
    }
#pragma unroll
    for (int mt = 0; mt < 2; mt++)
#pragma unroll
        for (int nt = 0; nt < 2; nt++) {
            mma_bf16(acc[mt][nt], aH[mt], bH[nt]);   // hi*hi
            mma_bf16(acc[mt][nt], aH[mt], bL[nt]);   // hi*lo
            mma_bf16(acc[mt][nt], aL[mt], bH[nt]);   // lo*hi
        }
}

// Pipelined GEMM phase, K in super-chunks of 32 (nch = #k16 chunks, even).
// EXACT R11 ring discipline at super-chunk granularity: 4 super-slots, prologue
// fills 3, wait_group(2), prefetch 3 ahead; the slot filled at iteration c,
// (c+3)%4 = (c-1)%4, was computed at iteration c-1 and is freed by the sync at
// the top of iteration c. Empty commits keep group counts exact.
__device__ void run_phase(CellSmem* sm, float acc[2][2][4],
    const __nv_bfloat16* xh, const __nv_bfloat16* xl, long long xstr,
    const __nv_bfloat16* wh, const __nv_bfloat16* wl, int ldW,
    int nch, int j0, int row, int half, int sel, int warp_m, int warp_n, int lane)
{
    int nsc = nch >> 1;
    __syncthreads();                        // all warps done with previous slot uses
#pragma unroll
    for (int i = 0; i < 3; i++) {
        if (i < nsc)
            fill_super(sm, i, xh, xl, xstr, wh, wl, ldW, i * 32, j0, row, half, sel);
        cp_commit();
    }
    for (int c = 0; c < nsc; c++) {
        cp_wait2();                         // super-chunk c landed (groups FIFO)
        __syncthreads();
        int nc = c + 3;
        if (nc < nsc)
            fill_super(sm, nc & 3, xh, xl, xstr, wh, wl, ldW, nc * 32,
                       j0, row, half, sel);
        cp_commit();
        compute_chunk(&sm->stg[(c & 3) * 2],     acc, warp_m, warp_n, lane);
        compute_chunk(&sm->stg[(c & 3) * 2 + 1], acc, warp_m, warp_n, lane);
    }
}

// Fused epilogue: fragments -> gate smem -> LSTM cell (c-state in registers)
// -> split-h store + mu partial. bsum/mwreg hoisted.
__device__ __forceinline__ void lstm_epilogue(CellSmem* sm, float acc[2][2][4],
    const float* __restrict__ bsum, float* creg,
    __nv_bfloat16* __restrict__ hH, __nv_bfloat16* __restrict__ hL,
    const float* mwreg, int t, int b0, int j0, int tid, int warp_m, int warp_n)
{
    int lane = tid & 31, grp = lane >> 2, tg = lane & 3;
#pragma unroll
    for (int mt = 0; mt < 2; mt++)
#pragma unroll
        for (int nt = 0; nt < 2; nt++) {
            int b = warp_m + mt * 16 + grp;
            int n = warp_n + nt * 8 + tg * 2;
            *(float2*)&sm->gate[b * 66 + n] = make_float2(acc[mt][nt][0], acc[mt][nt][1]);
            *(float2*)&sm->gate[(b + 8) * 66 + n] = make_float2(acc[mt][nt][2], acc[mt][nt][3]);
        }
    __syncthreads();
    int b = tid >> 2, q4 = tid & 3;
    int bg = b0 + b;
    float p = 0.0f;
    union { __nv_bfloat16 b[4]; uint2 v; } hpk, lpk;
#pragma unroll
    for (int q = 0; q < 4; q++) {
        int jj = q4 * 4 + q;
        float gi = sm->gate[b * 66 + jj]      + bsum[jj];
        float gf = sm->gate[b * 66 + 16 + jj] + bsum[16 + jj];
        float gg = sm->gate[b * 66 + 32 + jj] + bsum[32 + jj];
        float go = sm->gate[b * 66 + 48 + jj] + bsum[48 + jj];
        float c = sigmoidf_(gf) * creg[q] + sigmoidf_(gi) * tanhf(gg);
        float h = sigmoidf_(go) * tanhf(c);
        creg[q] = c;
        split_bf16(h, hpk.b[q], lpk.b[q]);
        p = fmaf(h, mwreg[q], p);
    }
    long long hidx = ((long long)t * Bq + bg) * Hq + j0 + q4 * 4;
    *(uint2*)&hH[hidx] = hpk.v;
    *(uint2*)&hL[hidx] = lpk.v;
    p += __shfl_xor_sync(0xffffffffu, p, 1);
    p += __shfl_xor_sync(0xffffffffu, p, 2);
    if (q4 == 0) atomicAdd(&g_mu[t & 1][bg], p);
}

// ==================== fused persistent kernel: all 160 timesteps ====================
__global__ void __launch_bounds__(256, 1) deepar_fused_kernel(
    const float* __restrict__ emb,
    const float* __restrict__ W_tgt, const float* __restrict__ b_tgt,
    const float* __restrict__ b_ih0, const float* __restrict__ b_hh0,
    const float* __restrict__ b_ih1, const float* __restrict__ b_hh1,
    const float* __restrict__ mu_w, const float* __restrict__ mu_b)
{
    extern __shared__ char smraw[];
    CellSmem* sm = (CellSmem*)smraw;
    int tid = threadIdx.x, lane = tid & 31, wid = tid >> 5;
    int warp_m = (wid & 1) * 32, warp_n = (wid >> 1) * 16;
    int sel = tid >> 7, row = (tid >> 1) & 63, half = tid & 1;
    int jb = blockIdx.x & 63, b0 = (blockIdx.x >> 6) * 64, j0 = jb * 16;
    unsigned bartgt = 0;

    // hoists: bias sums into smem, mu_w into registers, c-state into registers
    if (tid < 128) {
        int cell = tid >> 6, n = tid & 63;
        int g = n >> 4, jj = n & 15;
        int r = g * Hq + j0 + jj;
        sm->bsum[cell][n] = cell ? (b_ih1[r] + b_hh1[r]) : (b_ih0[r] + b_hh0[r]);
    }
    float mw[2][4], c0r[4], c1r[4];
#pragma unroll
    for (int q = 0; q < 4; q++) {
        int j = j0 + (tid & 3) * 4 + q;
        mw[0][q] = mu_w[2 * j];
        mw[1][q] = mu_w[2 * j + 1];
        c0r[q] = 0.0f;
        c1r[q] = 0.0f;
    }

    for (int t = 0; t < Tq; ++t) {
        // mask/mu flags for the label phase
        if (tid < 64) {
            int bg = b0 + tid;
            int um = (t > 0) && g_mask[bg * Tq + t];
            sm->um_s[tid] = (unsigned char)um;
            sm->mu_s[tid] = um ? (__ldcg(&g_mu[(t - 1) & 1][bg]) + mu_b[0]) : 0.0f;
        }

        float acc[2][2][4];
#pragma unroll
        for (int i = 0; i < 2; i++)
#pragma unroll
            for (int j = 0; j < 2; j++)
#pragma unroll
                for (int k = 0; k < 4; k++) acc[i][j][k] = 0.0f;

        // ---------------- cell0 ----------------
        {   // feat phase (K=512)
            long long off = ((long long)b0 * Tq + t) * Fq;
            run_phase(sm, acc, g_featH + off, g_featL + off, (long long)Tq * Fq,
                      g_WihH0, g_WihL0, IN0q, Fq / 16, j0, row, half, sel,
                      warp_m, warp_n, lane);
        }
        if (t > 0) {  // recurrent phase (K=1024)
            long long off = ((long long)(t - 1) * Bq + b0) * Hq;
            run_phase(sm, acc, g_h0h + off, g_h0l + off, (long long)Hq,
                      g_WhhH0, g_WhhL0, Hq, Hq / 16, j0, row, half, sel,
                      warp_m, warp_n, lane);
        }
        // label phase (K=64), standalone (pipeline fully drained of real groups):
        // x built on the fly from mask/mu feedback via plain STS into stg[0].
        __syncthreads();
        for (int lc = 0; lc < 4; lc++) {
#pragma unroll
            for (int i = 0; i < 4; i++) {
                int id = i * 256 + tid;
                int r = id >> 4, kk = id & 15, e = lc * 16 + kk;
                float v = sm->um_s[r] ? fmaf(sm->mu_s[r], W_tgt[e], b_tgt[e])
                                      : emb[((long long)(b0 + r) * Tq + t) * Eq + e];
                __nv_bfloat16 hi, lo;
                split_bf16(v, hi, lo);
                sm->stg[0].Ah[r * 24 + kk] = hi;
                sm->stg[0].Al[r * 24 + kk] = lo;
            }
#pragma unroll
            for (int i = 0; i < 8; i++) {
                int id = i * 256 + tid;
                int spl = id >> 10, rem = id & 1023;
                int n = rem >> 4, kk = rem & 15;
                int wrow = ((n >> 4) << 10) + j0 + (n & 15);
                long long off = (long long)wrow * IN0q + Fq + lc * 16 + kk;
                if (spl) sm->stg[0].Bl[n * 24 + kk] = g_WihL0[off];
                else     sm->stg[0].Bh[n * 24 + kk] = g_WihH0[off];
            }
            __syncthreads();
            compute_chunk(&sm->stg[0], acc, warp_m, warp_n, lane);
            __syncthreads();
        }
        lstm_epilogue(sm, acc, sm->bsum[0], c0r, g_h0h, g_h0l, mw[0],
                      t, b0, j0, tid, warp_m, warp_n);
        bartgt += 128;
        grid_barrier(bartgt);              // h0(t) visible to all CTAs

        // re-zero the consumed mu parity buffer (this step's atomics hit g_mu[t&1])
        if (blockIdx.x == 0 && tid < Bq) g_mu[1 - (t & 1)][tid] = 0.0f;

        // ---------------- cell1 ----------------
#pragma unroll
        for (int i = 0; i < 2; i++)
#pragma unroll
            for (int j = 0; j < 2; j++)
#pragma unroll
                for (int k = 0; k < 4; k++) acc[i][j][k] = 0.0f;
        {   // input phase: x = h0(t)
            long long off = ((long long)t * Bq + b0) * Hq;
            run_phase(sm, acc, g_h0h + off, g_h0l + off, (long long)Hq,
                      g_WihH1, g_WihL1, Hq, Hq / 16, j0, row, half, sel,
                      warp_m, warp_n, lane);
        }
        if (t > 0) {  // recurrent phase: x = h1(t-1)
            long long off = ((long long)(t - 1) * Bq + b0) * Hq;
            run_phase(sm, acc, g_h1h + off, g_h1l + off, (long long)Hq,
                      g_WhhH1, g_WhhL1, Hq, Hq / 16, j0, row, half, sel,
                      warp_m, warp_n, lane);
        }
        lstm_epilogue(sm, acc, sm->bsum[1], c1r, g_h1h, g_h1l, mw[1],
                      t, b0, j0, tid, warp_m, warp_n);
        bartgt += 128;
        grid_barrier(bartgt);              // h1(t) + mu(t) complete
    }
}

// ==================== final outputs ====================
__global__ void out_kernel(
    const float* __restrict__ mu_w, const float* __restrict__ mu_b,
    const float* __restrict__ sig_w, const float* __restrict__ sig_b,
    float* __restrict__ out)
{
    int t = blockIdx.x;
    int wid = threadIdx.x >> 5, lane = threadIdx.x & 31;
    const float2* mw2 = reinterpret_cast<const float2*>(mu_w);
    const float2* sw2 = reinterpret_cast<const float2*>(sig_w);
    for (int b = wid; b < Bq; b += 8) {
        long long base = ((long long)t * Bq + b) * Hq;
        float mp = 0.0f, sp = 0.0f;
        for (int h = lane; h < Hq; h += 32) {
            float a = __bfloat162float(g_h0h[base + h]) + __bfloat162float(g_h0l[base + h]);
            float c = __bfloat162float(g_h1h[base + h]) + __bfloat162float(g_h1l[base + h]);
            float2 m = mw2[h];
            float2 s = sw2[h];
            mp = fmaf(a, m.x, fmaf(c, m.y, mp));
            sp = fmaf(a, s.x, fmaf(c, s.y, sp));
        }
#pragma unroll
        for (int o = 16; o; o >>= 1) {
            mp += __shfl_xor_sync(0xffffffffu, mp, o);
            sp += __shfl_xor_sync(0xffffffffu, sp, o);
        }
        if (lane == 0) {
            float mu = mp + mu_b[0];
            float sv = sp + sig_b[0];
            float sig = fmaxf(sv, 0.0f) + log1pf(expf(-fabsf(sv)));
            out[(b * Tq + t) * 2 + 0] = mu;
            out[(b * Tq + t) * 2 + 1] = sig;
        }
    }
}

// ==================== launch ====================
extern "C" void kernel_launch(void* const* d_in, const int* in_sizes, int n_in,
                              void* d_out, int out_size)
{
    const float* feat  = (const float*)d_in[0];
    const float* emb   = (const float*)d_in[1];
    const unsigned char* mask_raw = (const unsigned char*)d_in[2];
    const float* W_ih0 = (const float*)d_in[3];
    const float* W_hh0 = (const float*)d_in[4];
    const float* b_ih0 = (const float*)d_in[5];
    const float* b_hh0 = (const float*)d_in[6];
    const float* W_ih1 = (const float*)d_in[7];
    const float* W_hh1 = (const float*)d_in[8];
    const float* b_ih1 = (const float*)d_in[9];
    const float* b_hh1 = (const float*)d_in[10];
    const float* W_tgt = (const float*)d_in[11];
    const float* b_tgt = (const float*)d_in[12];
    const float* mu_w  = (const float*)d_in[13];
    const float* mu_b  = (const float*)d_in[14];
    const float* sig_w = (const float*)d_in[15];
    const float* sig_b = (const float*)d_in[16];
    float* out = (float*)d_out;

    cudaFuncSetAttribute(deepar_fused_kernel, cudaFuncAttributeMaxDynamicSharedMemorySize,
                         CELL_SMEM_BYTES);

    mask_norm_kernel<<<1, 1024>>>(mask_raw);
    prep_split_kernel<<<1024, 256>>>(W_ih0, 4 * Hq * IN0q, 0);
    prep_split_kernel<<<1024, 256>>>(W_hh0, 4 * Hq * Hq, 1);
    prep_split_kernel<<<1024, 256>>>(W_ih1, 4 * Hq * Hq, 2);
    prep_split_kernel<<<1024, 256>>>(W_hh1, 4 * Hq * Hq, 3);
    prep_split_kernel<<<2048, 256>>>(feat, Bq * Tq * Fq, 4);

    deepar_fused_kernel<<<128, 256, CELL_SMEM_BYTES>>>(
        emb, W_tgt, b_tgt, b_ih0, b_hh0, b_ih1, b_hh1, mu_w, mu_b);

    out_kernel<<<Tq, 256>>>(mu_w, mu_b, sig_w, sig_b, out);
}